// round 1
// baseline (speedup 1.0000x reference)
#include <cuda_runtime.h>

#define B_   8
#define T_   2048
#define D_   1024
#define KQ_  128
#define TOPK 8
#define BT_  (B_ * T_)

// Output layout in d_out (float32):
//   [0, GATH_N)                      gathered [B,T,8,D]
//   [GATH_N, GATH_N+IDX_N)           topk_indices as float [B,T,8]
//   [GATH_N+IDX_N, +IDX_N)           sim_gathered [B,T,8]
#define GATH_N ((size_t)BT_ * TOPK * D_)   // 134217728
#define IDX_N  ((size_t)BT_ * TOPK)        // 131072

// Scratch (allocation-free rule: __device__ globals)
__device__ float g_q[BT_ * KQ_];
__device__ float g_k[BT_ * KQ_];
__device__ int   g_idx[BT_ * TOPK];

// ---------------------------------------------------------------------------
// Kernel A: fused Q/K projection.  q = x @ Wq^T + bq, k = x @ Wk^T + bk.
// GEMM M=16384, N=256 (128 q cols || 128 k cols), K=1024.
// Tile BM=64, BN=256, BK=32; 256 threads, 8x8 micro-tile.
// ---------------------------------------------------------------------------
__global__ __launch_bounds__(256) void proj_kernel(
    const float* __restrict__ x,
    const float* __restrict__ Wq, const float* __restrict__ bq,
    const float* __restrict__ Wk, const float* __restrict__ bk)
{
    __shared__ float As[32][68];    // x tile, transposed: As[d][m]
    __shared__ float Bs[32][260];   // W tile, transposed: Bs[d][n]

    const int tid = threadIdx.x;
    const int m0  = blockIdx.x * 64;
    const int ty  = tid >> 5;   // 0..7  -> rows ty*8..ty*8+7
    const int tx  = tid & 31;   // 0..31 -> cols tx*8..tx*8+7

    float acc[8][8];
#pragma unroll
    for (int i = 0; i < 8; i++)
#pragma unroll
        for (int j = 0; j < 8; j++) acc[i][j] = 0.f;

    for (int k0 = 0; k0 < D_; k0 += 32) {
        // load x tile: 64 rows x 32 d  (512 float4 / 256 thr = 2 each)
#pragma unroll
        for (int l = 0; l < 2; l++) {
            int e  = tid + l * 256;
            int r  = e >> 3;
            int c4 = e & 7;
            float4 v = *reinterpret_cast<const float4*>(
                &x[(size_t)(m0 + r) * D_ + k0 + c4 * 4]);
            As[c4 * 4 + 0][r] = v.x;
            As[c4 * 4 + 1][r] = v.y;
            As[c4 * 4 + 2][r] = v.z;
            As[c4 * 4 + 3][r] = v.w;
        }
        // load W tile: 256 rows x 32 d (2048 float4 / 256 thr = 8 each)
#pragma unroll
        for (int l = 0; l < 8; l++) {
            int e  = tid + l * 256;
            int n  = e >> 3;
            int c4 = e & 7;
            const float* Wsrc = (n < 128) ? &Wq[(size_t)n * D_]
                                          : &Wk[(size_t)(n - 128) * D_];
            float4 v = *reinterpret_cast<const float4*>(&Wsrc[k0 + c4 * 4]);
            Bs[c4 * 4 + 0][n] = v.x;
            Bs[c4 * 4 + 1][n] = v.y;
            Bs[c4 * 4 + 2][n] = v.z;
            Bs[c4 * 4 + 3][n] = v.w;
        }
        __syncthreads();

#pragma unroll 4
        for (int d = 0; d < 32; d++) {
            float4 a0 = *reinterpret_cast<const float4*>(&As[d][ty * 8]);
            float4 a1 = *reinterpret_cast<const float4*>(&As[d][ty * 8 + 4]);
            float4 b0 = *reinterpret_cast<const float4*>(&Bs[d][tx * 8]);
            float4 b1 = *reinterpret_cast<const float4*>(&Bs[d][tx * 8 + 4]);
            float a[8] = {a0.x, a0.y, a0.z, a0.w, a1.x, a1.y, a1.z, a1.w};
            float b[8] = {b0.x, b0.y, b0.z, b0.w, b1.x, b1.y, b1.z, b1.w};
#pragma unroll
            for (int i = 0; i < 8; i++)
#pragma unroll
                for (int j = 0; j < 8; j++) acc[i][j] += a[i] * b[j];
        }
        __syncthreads();
    }

    // epilogue: cols [0,128) -> q, [128,256) -> k  (8-col group never straddles)
    float* dst;
    const float* bias;
    int n0;
    if (tx < 16) { dst = g_q; bias = bq; n0 = tx * 8; }
    else         { dst = g_k; bias = bk; n0 = (tx - 16) * 8; }
    float bb[8];
#pragma unroll
    for (int j = 0; j < 8; j++) bb[j] = bias[n0 + j];

#pragma unroll
    for (int i = 0; i < 8; i++) {
        int m = m0 + ty * 8 + i;
        float4 v0 = make_float4(acc[i][0] + bb[0], acc[i][1] + bb[1],
                                acc[i][2] + bb[2], acc[i][3] + bb[3]);
        float4 v1 = make_float4(acc[i][4] + bb[4], acc[i][5] + bb[5],
                                acc[i][6] + bb[6], acc[i][7] + bb[7]);
        *reinterpret_cast<float4*>(&dst[(size_t)m * KQ_ + n0])     = v0;
        *reinterpret_cast<float4*>(&dst[(size_t)m * KQ_ + n0 + 4]) = v1;
    }
}

// ---------------------------------------------------------------------------
// Kernel B: fused sim = q @ k^T  +  per-row top-8 (with indices), never
// materializing sim in global memory.
// Block: 128 t-rows (one (b, t-tile)); loops over 16 s-tiles of 128.
// 256 threads, 8x8 micro-tile (KQ=128 fully resident, no k-loop).
// After each tile the sim values are staged into the K-tile smem and a
// dedicated thread per t-row folds them into its register top-8.
// ---------------------------------------------------------------------------
__global__ __launch_bounds__(256) void sim_topk_kernel(float* __restrict__ out)
{
    extern __shared__ float smem[];
    float* Qs = smem;                 // [128 d][132] : Qs[d*132 + t]
    float* Ks = smem + 128 * 132;     // [128 d][132] : Ks[d*132 + s]; reused as sim[t*132+s]

    const int tid = threadIdx.x;
    const int b   = blockIdx.y;
    const int t0  = blockIdx.x * 128;
    const int ty  = tid >> 4;   // 0..15 -> t rows ty*8..
    const int tx  = tid & 15;   // 0..15 -> s cols tx*8..

    // load Q tile (once): 128 rows x 128 d, transposed
    {
        const float* qbase = &g_q[((size_t)b * T_ + t0) * KQ_];
#pragma unroll
        for (int l = 0; l < 16; l++) {
            int e  = tid + l * 256;   // 0..4095
            int r  = e >> 5;          // t row
            int c4 = e & 31;          // float4 over d
            float4 v = *reinterpret_cast<const float4*>(&qbase[r * KQ_ + c4 * 4]);
            Qs[(c4 * 4 + 0) * 132 + r] = v.x;
            Qs[(c4 * 4 + 1) * 132 + r] = v.y;
            Qs[(c4 * 4 + 2) * 132 + r] = v.z;
            Qs[(c4 * 4 + 3) * 132 + r] = v.w;
        }
    }

    float topv[TOPK];
    int   topi[TOPK];
#pragma unroll
    for (int j = 0; j < TOPK; j++) { topv[j] = -3.402823466e38f; topi[j] = 0; }

    for (int st = 0; st < 16; st++) {
        __syncthreads();  // Q tile ready / previous scan done before Ks overwrite

        // load K tile: 128 s-rows x 128 d, transposed
        {
            const float* kbase = &g_k[((size_t)b * T_ + st * 128) * KQ_];
#pragma unroll
            for (int l = 0; l < 16; l++) {
                int e  = tid + l * 256;
                int r  = e >> 5;
                int c4 = e & 31;
                float4 v = *reinterpret_cast<const float4*>(&kbase[r * KQ_ + c4 * 4]);
                Ks[(c4 * 4 + 0) * 132 + r] = v.x;
                Ks[(c4 * 4 + 1) * 132 + r] = v.y;
                Ks[(c4 * 4 + 2) * 132 + r] = v.z;
                Ks[(c4 * 4 + 3) * 132 + r] = v.w;
            }
        }
        __syncthreads();

        float acc[8][8];
#pragma unroll
        for (int i = 0; i < 8; i++)
#pragma unroll
            for (int j = 0; j < 8; j++) acc[i][j] = 0.f;

#pragma unroll 4
        for (int d = 0; d < 128; d++) {
            float4 a0 = *reinterpret_cast<const float4*>(&Qs[d * 132 + ty * 8]);
            float4 a1 = *reinterpret_cast<const float4*>(&Qs[d * 132 + ty * 8 + 4]);
            float4 b0 = *reinterpret_cast<const float4*>(&Ks[d * 132 + tx * 8]);
            float4 b1 = *reinterpret_cast<const float4*>(&Ks[d * 132 + tx * 8 + 4]);
            float a[8] = {a0.x, a0.y, a0.z, a0.w, a1.x, a1.y, a1.z, a1.w};
            float bb[8] = {b0.x, b0.y, b0.z, b0.w, b1.x, b1.y, b1.z, b1.w};
#pragma unroll
            for (int i = 0; i < 8; i++)
#pragma unroll
                for (int j = 0; j < 8; j++) acc[i][j] += a[i] * bb[j];
        }
        __syncthreads();  // all reads of Ks done -> safe to overwrite with sims

        // stage sims: sim[t][s] into Ks region
#pragma unroll
        for (int i = 0; i < 8; i++) {
            int row = ty * 8 + i;
            float4 v0 = make_float4(acc[i][0], acc[i][1], acc[i][2], acc[i][3]);
            float4 v1 = make_float4(acc[i][4], acc[i][5], acc[i][6], acc[i][7]);
            *reinterpret_cast<float4*>(&Ks[row * 132 + tx * 8])     = v0;
            *reinterpret_cast<float4*>(&Ks[row * 132 + tx * 8 + 4]) = v1;
        }
        __syncthreads();

        // per-row top-8 fold: thread r owns t-row r. s scanned ascending ->
        // strict '>' insertion keeps lower index first on ties (XLA top_k).
        if (tid < 128) {
            const float* simrow = &Ks[tid * 132];
            int sbase = st * 128;
            for (int s = 0; s < 128; s++) {
                float v = simrow[s];
                if (v > topv[TOPK - 1]) {
                    topv[TOPK - 1] = v;
                    topi[TOPK - 1] = sbase + s;
#pragma unroll
                    for (int p = TOPK - 1; p > 0; p--) {
                        if (topv[p] > topv[p - 1]) {
                            float tv = topv[p]; topv[p] = topv[p - 1]; topv[p - 1] = tv;
                            int   ti = topi[p]; topi[p] = topi[p - 1]; topi[p - 1] = ti;
                        }
                    }
                }
            }
        }
    }

    // epilogue: write indices (as float + int scratch) and scaled sim values
    if (tid < 128) {
        const float scale = 0.08838834764831843f;  // 1/sqrt(128)
        size_t row = (size_t)b * T_ + (t0 + tid);
        float* out_idx = out + GATH_N;
        float* out_sim = out + GATH_N + IDX_N;
#pragma unroll
        for (int j = 0; j < TOPK; j++) {
            g_idx[row * TOPK + j]   = topi[j];
            out_idx[row * TOPK + j] = (float)topi[j];
            out_sim[row * TOPK + j] = topv[j] * scale;
        }
    }
}

// ---------------------------------------------------------------------------
// Kernel C: gather routed tokens. One block per (b,t,j) output row:
// copies x[b, idx, :] (1024 f32 = 256 float4) into out.
// ---------------------------------------------------------------------------
__global__ __launch_bounds__(256) void gather_kernel(
    const float* __restrict__ x, float* __restrict__ out)
{
    int r = blockIdx.x;                    // 0 .. B*T*8-1
    int b = r >> 14;                       // r / (T_*TOPK)
    int src_t = g_idx[r];
    const float4* src = reinterpret_cast<const float4*>(
        &x[((size_t)b * T_ + src_t) * D_]);
    float4* dst = reinterpret_cast<float4*>(&out[(size_t)r * D_]);
    dst[threadIdx.x] = src[threadIdx.x];
}

// ---------------------------------------------------------------------------
extern "C" void kernel_launch(void* const* d_in, const int* in_sizes, int n_in,
                              void* d_out, int out_size)
{
    const float* x  = (const float*)d_in[0];
    const float* Wq = (const float*)d_in[1];
    const float* bq = (const float*)d_in[2];
    const float* Wk = (const float*)d_in[3];
    const float* bk = (const float*)d_in[4];
    float* out = (float*)d_out;

    // A: projections
    proj_kernel<<<BT_ / 64, 256>>>(x, Wq, bq, Wk, bk);

    // B: fused sim + top-k
    int smemB = 2 * 128 * 132 * (int)sizeof(float);   // 135168 B
    cudaFuncSetAttribute(sim_topk_kernel,
                         cudaFuncAttributeMaxDynamicSharedMemorySize, smemB);
    dim3 gridB(T_ / 128, B_);
    sim_topk_kernel<<<gridB, 256, smemB>>>(out);

    // C: gather
    gather_kernel<<<BT_ * TOPK, 256>>>(x, out);
}